// round 2
// baseline (speedup 1.0000x reference)
#include <cuda_runtime.h>

#define NN 50000
#define NE 800000

// ---------------- scratch (__device__ globals: allocation-free) ----------------
__device__ __align__(16) float g_PQ  [NN * 512];   // [N,512]: P | Q
__device__ __align__(16) float g_m   [NE * 256];   // edge mlp hidden
__device__ __align__(16) float g_ef  [NE * 256];   // edge features
__device__ __align__(16) float g_agg [NN * 256];   // segment-sum of ef by row
__device__ __align__(16) float g_hmid[NN * 256];   // node mlp hidden
__device__ __align__(16) float g_phi [NE];         // coord mlp scalar per edge
__device__ __align__(16) float g_cnt [NN];
__device__ __align__(16) float g_csum[NN * 3];
__device__ __align__(16) float g_W1ab[512 * 256];  // packed [We1a ; We1b], ld=256
__device__ __align__(16) float g_wr  [256];        // We1[:,512] (radial column)
__device__ __align__(16) float g_b512[512];        // be1 | 0

// ---------------- helpers ----------------
__device__ __forceinline__ float siluf(float x) {
    return x * (1.0f / (1.0f + __expf(-x)));
}
__device__ __forceinline__ unsigned f2tf(float x) {
    unsigned r; asm("cvt.rna.tf32.f32 %0, %1;" : "=r"(r) : "f"(x)); return r;
}
__device__ __forceinline__ void mma8(float d[4], const unsigned a[4], const unsigned b[2]) {
    asm volatile(
        "mma.sync.aligned.m16n8k8.row.col.f32.tf32.tf32.f32 "
        "{%0,%1,%2,%3}, {%4,%5,%6,%7}, {%8,%9}, {%0,%1,%2,%3};\n"
        : "+f"(d[0]), "+f"(d[1]), "+f"(d[2]), "+f"(d[3])
        : "r"(a[0]), "r"(a[1]), "r"(a[2]), "r"(a[3]), "r"(b[0]), "r"(b[1]));
}

// ---------------- small kernels ----------------
__global__ void pack_weights(const float* __restrict__ We1, const float* __restrict__ be1) {
    int i = blockIdx.x * blockDim.x + threadIdx.x;
    if (i < 512 * 256) {
        int n = i >> 8, k = i & 255;
        g_W1ab[i] = (n < 256) ? We1[n * 513 + k] : We1[(n - 256) * 513 + 256 + k];
    }
    if (i < 256) g_wr[i] = We1[i * 513 + 512];
    if (i < 512) g_b512[i] = (i < 256) ? be1[i] : 0.0f;
}

__global__ void zero_scratch() {
    int i = blockIdx.x * blockDim.x + threadIdx.x;  // grid covers NN*256 = 12.8M
    if (i < NN * 256) g_agg[i] = 0.0f;
    if (i < NE)       g_phi[i] = 0.0f;
    if (i < NN * 3)   g_csum[i] = 0.0f;
    if (i < NN)       g_cnt[i] = 0.0f;
}

// one warp per edge: m = SiLU(P[row] + Q[col] + radial * wr)
__global__ void edge_m_kernel(const int* __restrict__ ei, const float* __restrict__ coord) {
    int e = blockIdx.x * 8 + (threadIdx.x >> 5);
    if (e >= NE) return;
    int lane = threadIdx.x & 31;
    int r = ei[e];
    int c = ei[NE + e];
    float dx = coord[3 * r + 0] - coord[3 * c + 0];
    float dy = coord[3 * r + 1] - coord[3 * c + 1];
    float dz = coord[3 * r + 2] - coord[3 * c + 2];
    float rad = dx * dx + dy * dy + dz * dz;
    const float4* PQ4 = (const float4*)g_PQ;
    const float4* wr4 = (const float4*)g_wr;
    float4* m4 = (float4*)g_m;
#pragma unroll
    for (int it = 0; it < 2; it++) {
        int q = lane + it * 32;                     // 0..63 (float4 index)
        float4 p  = PQ4[(size_t)r * 128 + q];       // P part
        float4 qq = PQ4[(size_t)c * 128 + 64 + q];  // Q part
        float4 w  = wr4[q];
        float4 v;
        v.x = siluf(p.x + qq.x + rad * w.x);
        v.y = siluf(p.y + qq.y + rad * w.y);
        v.z = siluf(p.z + qq.z + rad * w.z);
        v.w = siluf(p.w + qq.w + rad * w.w);
        m4[(size_t)e * 64 + q] = v;
    }
    if (lane == 0) atomicAdd(&g_cnt[r], 1.0f);
}

__global__ void edge_coord_kernel(const int* __restrict__ ei, const float* __restrict__ coord) {
    int e = blockIdx.x * blockDim.x + threadIdx.x;
    if (e >= NE) return;
    int r = ei[e], c = ei[NE + e];
    float p = g_phi[e];
    atomicAdd(&g_csum[3 * r + 0], (coord[3 * r + 0] - coord[3 * c + 0]) * p);
    atomicAdd(&g_csum[3 * r + 1], (coord[3 * r + 1] - coord[3 * c + 1]) * p);
    atomicAdd(&g_csum[3 * r + 2], (coord[3 * r + 2] - coord[3 * c + 2]) * p);
}

__global__ void coord_final_kernel(const float* __restrict__ coord, float* __restrict__ outc) {
    int i = blockIdx.x * blockDim.x + threadIdx.x;
    if (i >= NN) return;
    float d = fmaxf(g_cnt[i], 1.0f);
    outc[3 * i + 0] = coord[3 * i + 0] + g_csum[3 * i + 0] / d;
    outc[3 * i + 1] = coord[3 * i + 1] + g_csum[3 * i + 1] / d;
    outc[3 * i + 2] = coord[3 * i + 2] + g_csum[3 * i + 2] / d;
}

// ---------------- tf32 GEMM: C[M,Nout] = epilogue(A[M,K] @ W[Nout,K]^T) ----------------
#define BM 128
#define BN 256
#define BK 32
#define SST 36  // smem row stride in words; conflict-free fragment access

enum { MODE_PLAIN = 0, MODE_EF = 1, MODE_PHI = 2, MODE_CAT = 3, MODE_NODE2 = 4 };

template <int MODE>
__global__ void __launch_bounds__(256, 1)
gemm_kernel(const float* __restrict__ A, const float* __restrict__ A2,
            const float* __restrict__ W, const float* __restrict__ bias,
            float* __restrict__ C, int ldc, int M, int K,
            const int* __restrict__ rowidx, float* __restrict__ agg,
            const float* __restrict__ wc2, float* __restrict__ phi,
            const float* __restrict__ resid)
{
    extern __shared__ unsigned smem[];
    unsigned* Abase = smem;                  // 2 * BM*SST
    unsigned* Bbase = smem + 2 * BM * SST;   // 2 * BN*SST

    const int tid  = threadIdx.x;
    const int lane = tid & 31;
    const int warp = tid >> 5;
    const int wm = (warp & 1) * 64;
    const int wn = (warp >> 1) * 64;
    const int blockM = blockIdx.x * BM;
    const int blockN = blockIdx.y * BN;
    const int ldr = tid >> 3;          // 0..31
    const int lkq = (tid & 7) * 4;     // k offset within tile (quad)

    float acc[4][8][4];
#pragma unroll
    for (int i = 0; i < 4; i++)
#pragma unroll
        for (int j = 0; j < 8; j++)
#pragma unroll
            for (int q = 0; q < 4; q++) acc[i][j][q] = 0.0f;

    float4 ra[4];
    float4 rb[8];
    const int ktiles = K / BK;

    // ---- prologue: tile 0 -> smem buf 0 ----
    {
        const int k0 = 0;
#pragma unroll
        for (int i = 0; i < 4; i++) {
            int r = blockM + ldr + i * 32;
            const float* s;
            if (MODE == MODE_CAT)
                s = (k0 + lkq < 256) ? (A + (size_t)r * 256 + k0 + lkq)
                                     : (A2 + (size_t)r * 256 + (k0 + lkq - 256));
            else
                s = A + (size_t)r * K + k0 + lkq;
            ra[i] = (r < M) ? *(const float4*)s : make_float4(0, 0, 0, 0);
        }
#pragma unroll
        for (int i = 0; i < 8; i++) {
            int n = blockN + ldr + i * 32;
            rb[i] = *(const float4*)(W + (size_t)n * K + k0 + lkq);
        }
        unsigned* as = Abase;
        unsigned* bs = Bbase;
#pragma unroll
        for (int i = 0; i < 4; i++) {
            uint4 t; t.x = f2tf(ra[i].x); t.y = f2tf(ra[i].y); t.z = f2tf(ra[i].z); t.w = f2tf(ra[i].w);
            *(uint4*)(as + (ldr + i * 32) * SST + lkq) = t;
        }
#pragma unroll
        for (int i = 0; i < 8; i++) {
            uint4 t; t.x = f2tf(rb[i].x); t.y = f2tf(rb[i].y); t.z = f2tf(rb[i].z); t.w = f2tf(rb[i].w);
            *(uint4*)(bs + (ldr + i * 32) * SST + lkq) = t;
        }
    }
    __syncthreads();

    // ---- mainloop ----
    for (int t = 0; t < ktiles; ++t) {
        if (t + 1 < ktiles) {
            const int k0 = (t + 1) * BK;
#pragma unroll
            for (int i = 0; i < 4; i++) {
                int r = blockM + ldr + i * 32;
                const float* s;
                if (MODE == MODE_CAT)
                    s = (k0 + lkq < 256) ? (A + (size_t)r * 256 + k0 + lkq)
                                         : (A2 + (size_t)r * 256 + (k0 + lkq - 256));
                else
                    s = A + (size_t)r * K + k0 + lkq;
                ra[i] = (r < M) ? *(const float4*)s : make_float4(0, 0, 0, 0);
            }
#pragma unroll
            for (int i = 0; i < 8; i++) {
                int n = blockN + ldr + i * 32;
                rb[i] = *(const float4*)(W + (size_t)n * K + k0 + lkq);
            }
        }
        const unsigned* as = Abase + (t & 1) * BM * SST;
        const unsigned* bs = Bbase + (t & 1) * BN * SST;
#pragma unroll
        for (int kk = 0; kk < BK; kk += 8) {
            unsigned af[4][4];
#pragma unroll
            for (int mt = 0; mt < 4; mt++) {
                int r = wm + mt * 16 + (lane >> 2);
                int c = kk + (lane & 3);
                af[mt][0] = as[r * SST + c];
                af[mt][1] = as[(r + 8) * SST + c];
                af[mt][2] = as[r * SST + c + 4];
                af[mt][3] = as[(r + 8) * SST + c + 4];
            }
            unsigned bf[8][2];
#pragma unroll
            for (int nt = 0; nt < 8; nt++) {
                int n = wn + nt * 8 + (lane >> 2);
                int c = kk + (lane & 3);
                bf[nt][0] = bs[n * SST + c];
                bf[nt][1] = bs[n * SST + c + 4];
            }
#pragma unroll
            for (int mt = 0; mt < 4; mt++)
#pragma unroll
                for (int nt = 0; nt < 8; nt++)
                    mma8(acc[mt][nt], af[mt], bf[nt]);
        }
        if (t + 1 < ktiles) {
            unsigned* asw = Abase + ((t + 1) & 1) * BM * SST;
            unsigned* bsw = Bbase + ((t + 1) & 1) * BN * SST;
#pragma unroll
            for (int i = 0; i < 4; i++) {
                uint4 tt; tt.x = f2tf(ra[i].x); tt.y = f2tf(ra[i].y); tt.z = f2tf(ra[i].z); tt.w = f2tf(ra[i].w);
                *(uint4*)(asw + (ldr + i * 32) * SST + lkq) = tt;
            }
#pragma unroll
            for (int i = 0; i < 8; i++) {
                uint4 tt; tt.x = f2tf(rb[i].x); tt.y = f2tf(rb[i].y); tt.z = f2tf(rb[i].z); tt.w = f2tf(rb[i].w);
                *(uint4*)(bsw + (ldr + i * 32) * SST + lkq) = tt;
            }
            __syncthreads();
        }
    }

    // ---- epilogue ----
#pragma unroll
    for (int mt = 0; mt < 4; mt++) {
        int row0 = blockM + wm + mt * 16 + (lane >> 2);
        float pp[2]; pp[0] = 0.0f; pp[1] = 0.0f;
        int e0 = 0, e1 = 0;
        if (MODE == MODE_EF) {
            e0 = (row0 < M) ? rowidx[row0] : 0;
            e1 = (row0 + 8 < M) ? rowidx[row0 + 8] : 0;
        }
#pragma unroll
        for (int h2 = 0; h2 < 2; h2++) {
            int row = row0 + h2 * 8;
            if (row < M) {
#pragma unroll
                for (int nt = 0; nt < 8; nt++) {
                    int col = blockN + wn + nt * 8 + (lane & 3) * 2;
                    float v0 = acc[mt][nt][h2 * 2 + 0];
                    float v1 = acc[mt][nt][h2 * 2 + 1];
                    if (MODE == MODE_PLAIN) {
                        if (bias) { v0 += bias[col]; v1 += bias[col + 1]; }
                        *(float2*)&C[(size_t)row * ldc + col] = make_float2(v0, v1);
                    } else if (MODE == MODE_EF) {
                        v0 = siluf(v0 + bias[col]);
                        v1 = siluf(v1 + bias[col + 1]);
                        *(float2*)&C[(size_t)row * ldc + col] = make_float2(v0, v1);
                        int eidx = h2 ? e1 : e0;
                        atomicAdd(&agg[(size_t)eidx * 256 + col], v0);
                        atomicAdd(&agg[(size_t)eidx * 256 + col + 1], v1);
                    } else if (MODE == MODE_PHI) {
                        v0 = siluf(v0 + bias[col]);
                        v1 = siluf(v1 + bias[col + 1]);
                        pp[h2] += v0 * wc2[col] + v1 * wc2[col + 1];
                    } else if (MODE == MODE_CAT) {
                        v0 = siluf(v0 + bias[col]);
                        v1 = siluf(v1 + bias[col + 1]);
                        *(float2*)&C[(size_t)row * ldc + col] = make_float2(v0, v1);
                    } else {  // MODE_NODE2
                        v0 += bias[col] + resid[(size_t)row * ldc + col];
                        v1 += bias[col + 1] + resid[(size_t)row * ldc + col + 1];
                        *(float2*)&C[(size_t)row * ldc + col] = make_float2(v0, v1);
                    }
                }
            }
        }
        if (MODE == MODE_PHI) {
            pp[0] += __shfl_xor_sync(0xffffffffu, pp[0], 1);
            pp[0] += __shfl_xor_sync(0xffffffffu, pp[0], 2);
            pp[1] += __shfl_xor_sync(0xffffffffu, pp[1], 1);
            pp[1] += __shfl_xor_sync(0xffffffffu, pp[1], 2);
            if ((lane & 3) == 0) {
                if (row0 < M) atomicAdd(&phi[row0], pp[0]);
                if (row0 + 8 < M) atomicAdd(&phi[row0 + 8], pp[1]);
            }
        }
    }
}

// ---------------- host ----------------
extern "C" void kernel_launch(void* const* d_in, const int* in_sizes, int n_in,
                              void* d_out, int out_size)
{
    (void)in_sizes; (void)n_in; (void)out_size;
    const float* h     = (const float*)d_in[0];
    const int*   ei    = (const int*)  d_in[1];
    const float* coord = (const float*)d_in[2];
    const float* We1   = (const float*)d_in[3];
    const float* be1   = (const float*)d_in[4];
    const float* We2   = (const float*)d_in[5];
    const float* be2   = (const float*)d_in[6];
    const float* Wn1   = (const float*)d_in[7];
    const float* bn1   = (const float*)d_in[8];
    const float* Wn2   = (const float*)d_in[9];
    const float* bn2   = (const float*)d_in[10];
    const float* Wc1   = (const float*)d_in[11];
    const float* bc1   = (const float*)d_in[12];
    const float* Wc2   = (const float*)d_in[13];
    float* outh = (float*)d_out;
    float* outc = outh + (size_t)NN * 256;

    float *pPQ, *pm, *pef, *pagg, *phmid, *pphi, *pW1ab, *pb512;
    cudaGetSymbolAddress((void**)&pPQ,   g_PQ);
    cudaGetSymbolAddress((void**)&pm,    g_m);
    cudaGetSymbolAddress((void**)&pef,   g_ef);
    cudaGetSymbolAddress((void**)&pagg,  g_agg);
    cudaGetSymbolAddress((void**)&phmid, g_hmid);
    cudaGetSymbolAddress((void**)&pphi,  g_phi);
    cudaGetSymbolAddress((void**)&pW1ab, g_W1ab);
    cudaGetSymbolAddress((void**)&pb512, g_b512);

    const int SMEMB = (2 * BM * SST + 2 * BN * SST) * 4;  // 110592 bytes
    static bool attr_done = false;
    cudaFuncSetAttribute((const void*)gemm_kernel<MODE_PLAIN>, cudaFuncAttributeMaxDynamicSharedMemorySize, SMEMB);
    cudaFuncSetAttribute((const void*)gemm_kernel<MODE_EF>,    cudaFuncAttributeMaxDynamicSharedMemorySize, SMEMB);
    cudaFuncSetAttribute((const void*)gemm_kernel<MODE_PHI>,   cudaFuncAttributeMaxDynamicSharedMemorySize, SMEMB);
    cudaFuncSetAttribute((const void*)gemm_kernel<MODE_CAT>,   cudaFuncAttributeMaxDynamicSharedMemorySize, SMEMB);
    cudaFuncSetAttribute((const void*)gemm_kernel<MODE_NODE2>, cudaFuncAttributeMaxDynamicSharedMemorySize, SMEMB);
    (void)attr_done;

    pack_weights<<<512, 256>>>(We1, be1);
    zero_scratch<<<50000, 256>>>();

    // PQ = h @ [We1a;We1b]^T + [be1;0] : M=NN, K=256, Nout=512
    gemm_kernel<MODE_PLAIN><<<dim3((NN + BM - 1) / BM, 2), 256, SMEMB>>>(
        h, nullptr, pW1ab, pb512, pPQ, 512, NN, 256,
        nullptr, nullptr, nullptr, nullptr, nullptr);

    // per-edge m = SiLU(P[row]+Q[col]+radial*wr); also counts cnt[row]
    edge_m_kernel<<<(NE + 7) / 8, 256>>>(ei, coord);

    // ef = SiLU(m @ We2^T + be2), scatter-add into agg[row]
    gemm_kernel<MODE_EF><<<dim3(NE / BM, 1), 256, SMEMB>>>(
        pm, nullptr, We2, be2, pef, 256, NE, 256,
        ei, pagg, nullptr, nullptr, nullptr);

    // phi = SiLU(ef @ Wc1^T + bc1) @ Wc2^T  (Nout=1 folded into epilogue)
    gemm_kernel<MODE_PHI><<<dim3(NE / BM, 1), 256, SMEMB>>>(
        pef, nullptr, Wc1, bc1, nullptr, 256, NE, 256,
        nullptr, nullptr, Wc2, pphi, nullptr);

    // coord aggregation + final coord output
    edge_coord_kernel<<<(NE + 255) / 256, 256>>>(ei, coord);
    coord_final_kernel<<<(NN + 255) / 256, 256>>>(coord, outc);

    // hmid = SiLU([h | agg] @ Wn1^T + bn1) : K=512 concat
    gemm_kernel<MODE_CAT><<<dim3((NN + BM - 1) / BM, 1), 256, SMEMB>>>(
        h, pagg, Wn1, bn1, phmid, 256, NN, 512,
        nullptr, nullptr, nullptr, nullptr, nullptr);

    // h_out = hmid @ Wn2^T + bn2 + h (residual)
    gemm_kernel<MODE_NODE2><<<dim3((NN + BM - 1) / BM, 1), 256, SMEMB>>>(
        phmid, nullptr, Wn2, bn2, outh, 256, NN, 256,
        nullptr, nullptr, nullptr, nullptr, h);
}